// round 7
// baseline (speedup 1.0000x reference)
#include <cuda_runtime.h>

#define N_USERS 200000
#define N_SPOTS 50000
#define N_NODES (N_USERS + N_SPOTS)
#define N_EDGES 3200000
#define D 64
#define D2 (D / 2)   // 32 float2 per row
#define D4 (D / 4)   // 16 float4 per row

// Fixed-stride adjacency. Degrees ~ Poisson(16)/Poisson(64); caps 96/192 have
// ~e^-50 overflow probability; writes are bounds-guarded (clamped, never OOB).
#define CAP_U 96
#define CAP_S 192

// Scratch (__device__ globals; allocations forbidden).
// Combined node index space: [0, N_USERS) users, [N_USERS, N_NODES) spots.
__device__ int   g_cnt[N_NODES];
__device__ float g_isq[N_NODES];
__device__ int   g_adj_u[(long long)N_USERS * CAP_U]; // user -> spot partners
__device__ int   g_adj_s[(long long)N_SPOTS * CAP_S]; // spot -> user partners
__device__ float g_ux[(long long)N_USERS * D];        // pre-scaled user rows
__device__ float g_sx[(long long)N_SPOTS * D];        // pre-scaled spot rows

__global__ void __launch_bounds__(256) zero_kernel() {
    int i = blockIdx.x * blockDim.x + threadIdx.x;
    if (i < N_NODES) g_cnt[i] = 0;
}

// Fused degree+fill: one atomic produces slot AND final degree. 4 edges per
// thread via int4 loads; 8 independent atomics then 8 guarded stores.
__global__ void __launch_bounds__(256) fill_kernel(const int4* __restrict__ user_idx4,
                                                   const int4* __restrict__ spot_idx4) {
    int t = blockIdx.x * blockDim.x + threadIdx.x;
    if (t >= N_EDGES / 4) return;
    int4 u = __ldg(&user_idx4[t]);
    int4 s = __ldg(&spot_idx4[t]);

    int au0 = atomicAdd(&g_cnt[u.x], 1);
    int au1 = atomicAdd(&g_cnt[u.y], 1);
    int au2 = atomicAdd(&g_cnt[u.z], 1);
    int au3 = atomicAdd(&g_cnt[u.w], 1);
    int as0 = atomicAdd(&g_cnt[N_USERS + s.x], 1);
    int as1 = atomicAdd(&g_cnt[N_USERS + s.y], 1);
    int as2 = atomicAdd(&g_cnt[N_USERS + s.z], 1);
    int as3 = atomicAdd(&g_cnt[N_USERS + s.w], 1);

    if (au0 < CAP_U) g_adj_u[(long long)u.x * CAP_U + au0] = s.x;
    if (au1 < CAP_U) g_adj_u[(long long)u.y * CAP_U + au1] = s.y;
    if (au2 < CAP_U) g_adj_u[(long long)u.z * CAP_U + au2] = s.z;
    if (au3 < CAP_U) g_adj_u[(long long)u.w * CAP_U + au3] = s.w;
    if (as0 < CAP_S) g_adj_s[(long long)s.x * CAP_S + as0] = u.x;
    if (as1 < CAP_S) g_adj_s[(long long)s.y * CAP_S + as1] = u.y;
    if (as2 < CAP_S) g_adj_s[(long long)s.z * CAP_S + as2] = u.z;
    if (as3 < CAP_S) g_adj_s[(long long)s.w * CAP_S + as3] = u.w;
}

// Pre-scale all rows by their node's inv-sqrt degree (float4 per thread) and
// materialize g_isq (one writer per node).
__global__ void __launch_bounds__(256) prescale_kernel(const float* __restrict__ user_x,
                                                       const float* __restrict__ spot_x) {
    long long i = (long long)blockIdx.x * blockDim.x + threadIdx.x;
    if (i >= (long long)N_NODES * D4) return;
    int node = (int)(i >> 4);
    int dg = g_cnt[node];
    float q = rsqrtf(dg == 0 ? 1e-6f : (float)dg);
    if ((i & 15) == 0) g_isq[node] = q;

    const float4* src;
    float4* dst;
    if (node < N_USERS) {
        src = (const float4*)user_x;
        dst = (float4*)g_ux;
    } else {
        src = (const float4*)spot_x + (long long)(node - N_USERS) * D4 - (long long)node * D4;
        dst = (float4*)g_sx + (long long)(node - N_USERS) * D4 - (long long)node * D4;
    }
    float4 v = __ldg(&src[i]);
    v.x *= q; v.y *= q; v.z *= q; v.w *= q;
    dst[i] = v;
}

// One warp per node; lane owns one float2 column chunk. Partner indices are
// fetched 32-at-a-time with ONE coalesced LDG, broadcast via shfl. Rows are
// pre-scaled, so inner body is load+add only. ~2 L1 wavefronts per edge.
__global__ void __launch_bounds__(256) gather_kernel(float* __restrict__ out) {
    int n = (blockIdx.x * blockDim.x + threadIdx.x) >> 5;
    if (n >= N_NODES) return;
    int lane = threadIdx.x & 31;

    bool is_user = (n < N_USERS);
    int deg = g_cnt[n];
    const int* __restrict__ adj;
    int cap;
    const float2* __restrict__ px;
    if (is_user) {
        adj = g_adj_u + (long long)n * CAP_U; cap = CAP_U;
        px = (const float2*)g_sx;                       // partners are spots
    } else {
        adj = g_adj_s + (long long)(n - N_USERS) * CAP_S; cap = CAP_S;
        px = (const float2*)g_ux;                       // partners are users
    }
    int end = min(deg, cap);

    float accx = 0.f, accy = 0.f;

    int base = 0;
    for (; base + 32 <= end; base += 32) {
        int p = __ldg(&adj[base + lane]);
        #pragma unroll
        for (int k = 0; k < 32; ++k) {
            int pk = __shfl_sync(0xffffffffu, p, k);
            float2 v = __ldg(&px[pk * D2 + lane]);
            accx += v.x; accy += v.y;
        }
    }
    int rem = end - base;
    if (rem > 0) {
        // Safe: base+31 < cap always (base multiple of 32, base < end <= cap).
        int p = __ldg(&adj[base + lane]);
        #pragma unroll 4
        for (int k = 0; k < rem; ++k) {
            int pk = __shfl_sync(0xffffffffu, p, k);
            float2 v = __ldg(&px[pk * D2 + lane]);
            accx += v.x; accy += v.y;
        }
    }

    float sc = g_isq[n];
    float2 r = make_float2(accx * sc, accy * sc);
    // Output layout [user rows][spot rows] == combined node index space.
    ((float2*)out)[n * D2 + lane] = r;
}

extern "C" void kernel_launch(void* const* d_in, const int* in_sizes, int n_in,
                              void* d_out, int out_size) {
    const float* user_x   = (const float*)d_in[0];
    const float* spot_x   = (const float*)d_in[1];
    const int*   user_idx = (const int*)d_in[2];
    const int*   spot_idx = (const int*)d_in[3];
    float* out = (float*)d_out;

    zero_kernel<<<(N_NODES + 255) / 256, 256>>>();

    int e4 = N_EDGES / 4;  // 800000
    fill_kernel<<<(e4 + 255) / 256, 256>>>((const int4*)user_idx, (const int4*)spot_idx);

    long long ps_threads = (long long)N_NODES * D4;
    prescale_kernel<<<(int)((ps_threads + 255) / 256), 256>>>(user_x, spot_x);

    long long gather_threads = (long long)N_NODES * 32;
    int gather_blocks = (int)((gather_threads + 255) / 256);
    gather_kernel<<<gather_blocks, 256>>>(out);
}

// round 8
// speedup vs baseline: 1.0582x; 1.0582x over previous
#include <cuda_runtime.h>

#define N_USERS 200000
#define N_SPOTS 50000
#define N_NODES (N_USERS + N_SPOTS)
#define N_EDGES 3200000
#define D 64
#define D4 (D / 4)   // 16 float4 per row

// Fixed-stride adjacency. Degrees ~ Poisson(16)/Poisson(64); caps 96/192 have
// ~e^-50 overflow probability; writes are bounds-guarded (clamped, never OOB).
// Both caps divisible by 16 (index-chunk size).
#define CAP_U 96
#define CAP_S 192

// Scratch (__device__ globals; allocations forbidden).
// Combined node index space: [0, N_USERS) users, [N_USERS, N_NODES) spots.
__device__ int   g_cnt[N_NODES];
__device__ float g_isq[N_NODES];
__device__ int   g_adj_u[(long long)N_USERS * CAP_U]; // user -> spot partners
__device__ int   g_adj_s[(long long)N_SPOTS * CAP_S]; // spot -> user partners
__device__ float g_ux[(long long)N_USERS * D];        // pre-scaled user rows
__device__ float g_sx[(long long)N_SPOTS * D];        // pre-scaled spot rows

__device__ __forceinline__ void add_f32x2(unsigned long long& a, unsigned long long b) {
    asm("add.rn.f32x2 %0, %0, %1;" : "+l"(a) : "l"(b));
}
__device__ __forceinline__ unsigned long long mul_f32x2(unsigned long long a, unsigned long long b) {
    unsigned long long r;
    asm("mul.rn.f32x2 %0, %1, %2;" : "=l"(r) : "l"(a), "l"(b));
    return r;
}

__global__ void __launch_bounds__(256) zero_kernel() {
    int i = blockIdx.x * blockDim.x + threadIdx.x;
    if (i < N_NODES) g_cnt[i] = 0;
}

// Fused degree+fill: one atomic produces slot AND final degree. 4 edges per
// thread via int4 loads; 8 independent atomics then 8 guarded stores.
__global__ void __launch_bounds__(256) fill_kernel(const int4* __restrict__ user_idx4,
                                                   const int4* __restrict__ spot_idx4) {
    int t = blockIdx.x * blockDim.x + threadIdx.x;
    if (t >= N_EDGES / 4) return;
    int4 u = __ldg(&user_idx4[t]);
    int4 s = __ldg(&spot_idx4[t]);

    int au0 = atomicAdd(&g_cnt[u.x], 1);
    int au1 = atomicAdd(&g_cnt[u.y], 1);
    int au2 = atomicAdd(&g_cnt[u.z], 1);
    int au3 = atomicAdd(&g_cnt[u.w], 1);
    int as0 = atomicAdd(&g_cnt[N_USERS + s.x], 1);
    int as1 = atomicAdd(&g_cnt[N_USERS + s.y], 1);
    int as2 = atomicAdd(&g_cnt[N_USERS + s.z], 1);
    int as3 = atomicAdd(&g_cnt[N_USERS + s.w], 1);

    if (au0 < CAP_U) g_adj_u[(long long)u.x * CAP_U + au0] = s.x;
    if (au1 < CAP_U) g_adj_u[(long long)u.y * CAP_U + au1] = s.y;
    if (au2 < CAP_U) g_adj_u[(long long)u.z * CAP_U + au2] = s.z;
    if (au3 < CAP_U) g_adj_u[(long long)u.w * CAP_U + au3] = s.w;
    if (as0 < CAP_S) g_adj_s[(long long)s.x * CAP_S + as0] = u.x;
    if (as1 < CAP_S) g_adj_s[(long long)s.y * CAP_S + as1] = u.y;
    if (as2 < CAP_S) g_adj_s[(long long)s.z * CAP_S + as2] = u.z;
    if (as3 < CAP_S) g_adj_s[(long long)s.w * CAP_S + as3] = u.w;
}

// Pre-scale all rows by their node's inv-sqrt degree (float4 per thread) and
// materialize g_isq (one writer per node).
__global__ void __launch_bounds__(256) prescale_kernel(const float* __restrict__ user_x,
                                                       const float* __restrict__ spot_x) {
    long long i = (long long)blockIdx.x * blockDim.x + threadIdx.x;
    if (i >= (long long)N_NODES * D4) return;
    int node = (int)(i >> 4);
    int dg = g_cnt[node];
    float q = rsqrtf(dg == 0 ? 1e-6f : (float)dg);
    if ((i & 15) == 0) g_isq[node] = q;

    float4 v;
    if (node < N_USERS) {
        v = __ldg(&((const float4*)user_x)[i]);
        v.x *= q; v.y *= q; v.z *= q; v.w *= q;
        ((float4*)g_ux)[i] = v;
    } else {
        long long j = i - (long long)N_USERS * D4;
        v = __ldg(&((const float4*)spot_x)[j]);
        v.x *= q; v.y *= q; v.z *= q; v.w *= q;
        ((float4*)g_sx)[j] = v;
    }
}

// Two nodes per warp (16 lanes each, float4 per lane). One row-LDG covers two
// edges; indices fetched 16-per-half with one coalesced LDG; shfl broadcast.
// Packed f32x2 accumulation. Plain stores, zero atomics, no output memset.
__global__ void __launch_bounds__(256) gather_kernel(float* __restrict__ out) {
    int warp = (blockIdx.x * blockDim.x + threadIdx.x) >> 5;
    int lane = threadIdx.x & 31;
    int half16 = lane & 16;       // 0 or 16
    int col = lane & 15;

    int n = warp * 2 + (half16 >> 4);   // N_NODES even: both halves valid
    if (n >= N_NODES) return;

    bool is_user = (n < N_USERS);
    int deg = g_cnt[n];
    const int* __restrict__ adj;
    const ulonglong2* __restrict__ px;  // pre-scaled partner rows, 16B chunks
    int end;
    if (is_user) {
        adj = g_adj_u + (long long)n * CAP_U;
        px = (const ulonglong2*)g_sx;
        end = min(deg, CAP_U);
    } else {
        adj = g_adj_s + (long long)(n - N_USERS) * CAP_S;
        px = (const ulonglong2*)g_ux;
        end = min(deg, CAP_S);
    }
    int max_end = max(end, __shfl_xor_sync(0xffffffffu, end, 16));

    unsigned long long acc0 = 0, acc1 = 0;  // packed {0.f,0.f} bit pattern == 0

    for (int base = 0; base < max_end; base += 16) {
        int p = 0;
        if (base < end) p = __ldg(&adj[base + col]);  // within cap: base<end<=cap, cap%16==0
        #pragma unroll
        for (int k = 0; k < 16; ++k) {
            int pk = __shfl_sync(0xffffffffu, p, half16 + k);
            if (base + k < end) {
                ulonglong2 v = __ldg(&px[pk * D4 + col]);
                add_f32x2(acc0, v.x);
                add_f32x2(acc1, v.y);
            }
        }
    }

    float sc = g_isq[n];
    unsigned long long scp;
    asm("mov.b64 %0, {%1, %1};" : "=l"(scp) : "f"(sc));
    ulonglong2 r;
    r.x = mul_f32x2(acc0, scp);
    r.y = mul_f32x2(acc1, scp);
    // Output layout [user rows][spot rows] == combined node index space.
    ((ulonglong2*)out)[(long long)n * D4 + col] = r;
}

extern "C" void kernel_launch(void* const* d_in, const int* in_sizes, int n_in,
                              void* d_out, int out_size) {
    const float* user_x   = (const float*)d_in[0];
    const float* spot_x   = (const float*)d_in[1];
    const int*   user_idx = (const int*)d_in[2];
    const int*   spot_idx = (const int*)d_in[3];
    float* out = (float*)d_out;

    zero_kernel<<<(N_NODES + 255) / 256, 256>>>();

    int e4 = N_EDGES / 4;  // 800000
    fill_kernel<<<(e4 + 255) / 256, 256>>>((const int4*)user_idx, (const int4*)spot_idx);

    long long ps_threads = (long long)N_NODES * D4;
    prescale_kernel<<<(int)((ps_threads + 255) / 256), 256>>>(user_x, spot_x);

    long long gather_threads = (long long)(N_NODES / 2) * 32;  // 2 nodes per warp
    int gather_blocks = (int)((gather_threads + 255) / 256);
    gather_kernel<<<gather_blocks, 256>>>(out);
}